// round 4
// baseline (speedup 1.0000x reference)
#include <cuda_runtime.h>

// Problem constants
#define BB 128
#define JJ 17
#define YY 96
#define XX 72
#define YX (YY * XX)                 // 6912
#define NTOT (BB * JJ * YX)          // 15,040,512 elements per plane
#define N4 (NTOT / 4)                // 3,760,128 float4 chunks per plane

#define NBLK 1184                    // 148 SMs * 8 blocks (2048 thr/SM, one wave)
#define NTHR 256

static __device__ double g_partials[NBLK];

__global__ void __launch_bounds__(NTHR) regloss_reduce(
    const float* __restrict__ loc,
    const float* __restrict__ cord,
    const float* __restrict__ tw)
{
    const float4* __restrict__ loc0 = reinterpret_cast<const float4*>(loc);
    const float4* __restrict__ loc1 = reinterpret_cast<const float4*>(loc + NTOT);

    float acc = 0.0f;
    const int stride = gridDim.x * blockDim.x;
    for (int i = blockIdx.x * blockDim.x + threadIdx.x; i < N4; i += stride) {
        const int n  = i * 4;
        const int m  = n / YX;            // = b*J + j  (same flat index for tw AND cord!)
        const int p  = n - m * YX;
        const int y  = p / XX;
        const int x0 = p - y * XX;

        const float w  = __ldg(tw + m);
        const float cx = __ldg(cord + m);            // cord[0] flat index == m
        const float cy = __ldg(cord + JJ * BB + m);  // cord[1]

        const float4 lx = __ldg(loc0 + i);
        const float4 ly = __ldg(loc1 + i);

        // int32-truncated ground-truth shifts (toward zero, matches astype(int32))
        const float gy  = truncf((float)y - cy);
        const float gx0 = truncf((float)(x0 + 0) - cx);
        const float gx1 = truncf((float)(x0 + 1) - cx);
        const float gx2 = truncf((float)(x0 + 2) - cx);
        const float gx3 = truncf((float)(x0 + 3) - cx);

        float d;
        d = (lx.x - gx0) * w; acc = fmaf(d, d, acc);
        d = (lx.y - gx1) * w; acc = fmaf(d, d, acc);
        d = (lx.z - gx2) * w; acc = fmaf(d, d, acc);
        d = (lx.w - gx3) * w; acc = fmaf(d, d, acc);
        d = (ly.x - gy)  * w; acc = fmaf(d, d, acc);
        d = (ly.y - gy)  * w; acc = fmaf(d, d, acc);
        d = (ly.z - gy)  * w; acc = fmaf(d, d, acc);
        d = (ly.w - gy)  * w; acc = fmaf(d, d, acc);
    }

    // Block tree reduction in shared memory (deterministic)
    __shared__ float sm[NTHR];
    sm[threadIdx.x] = acc;
    __syncthreads();
    #pragma unroll
    for (int s = NTHR / 2; s >= 32; s >>= 1) {
        if (threadIdx.x < s) sm[threadIdx.x] += sm[threadIdx.x + s];
        __syncthreads();
    }
    if (threadIdx.x < 32) {
        float v = sm[threadIdx.x];
        #pragma unroll
        for (int off = 16; off > 0; off >>= 1)
            v += __shfl_down_sync(0xFFFFFFFFu, v, off);
        if (threadIdx.x == 0)
            g_partials[blockIdx.x] = (double)v;
    }
}

__global__ void __launch_bounds__(NTHR) regloss_finalize(float* __restrict__ out)
{
    __shared__ double sm[NTHR];
    double s = 0.0;
    for (int i = threadIdx.x; i < NBLK; i += NTHR)
        s += g_partials[i];
    sm[threadIdx.x] = s;
    __syncthreads();
    #pragma unroll
    for (int st = NTHR / 2; st > 0; st >>= 1) {
        if (threadIdx.x < st) sm[threadIdx.x] += sm[threadIdx.x + st];
        __syncthreads();
    }
    if (threadIdx.x == 0) {
        // loss = 0.5 * Sigma / (B*YX) / J
        const double scale = 0.5 / (double)NTOT;
        out[0] = (float)(sm[0] * scale);
    }
}

extern "C" void kernel_launch(void* const* d_in, const int* in_sizes, int n_in,
                              void* d_out, int out_size)
{
    const float* loc  = (const float*)d_in[0];   // (2, B, J, Y, X) fp32
    const float* cord = (const float*)d_in[1];   // (2, J, B) fp32
    const float* tw   = (const float*)d_in[2];   // (B, J, 1) fp32
    float* out = (float*)d_out;

    regloss_reduce<<<NBLK, NTHR>>>(loc, cord, tw);
    regloss_finalize<<<1, NTHR>>>(out);
}